// round 6
// baseline (speedup 1.0000x reference)
#include <cuda_runtime.h>

#define NV 512      // nodes
#define HN 128      // WL hash buckets
#define CH 256      // duplicated row stride (2*HN)
#define EE 2048     // original edges
#define E2 4096     // symmetrized directed edges
#define FF 16       // filter graphs
#define MM 8        // filter graph nodes
#define LL 16       // labels
#define NBLK 148    // persistent grid (B300: 148 SMs)

// ---- static device scratch (no allocation allowed) ----
// C/U stored DUPLICATED: value k lives at [2k] and [2k+1] (f32x2 broadcast packs for free)
__device__ __align__(16) float d_C[(size_t)NV * NV * CH];
__device__ __align__(16) float d_U[(size_t)NV * NV * CH];
__device__ __align__(16) float d_ego[NV * 4 * HN];
__device__ __align__(16) float d_filt[FF * 4 * HN];
__device__ float d_nf[FF];
__device__ int d_deg[NV], d_off[NV + 1], d_fill[NV];
__device__ int d_adj[E2];
__device__ int d_nb[NV];        // node bucket index
__device__ int d_bucket[LL];    // label -> bucket
__device__ unsigned d_mask[NV * 16];   // per-root 512-bit reach mask
__device__ int d_ctr;           // persistent-kernel root counter

#define HBAR() asm volatile("bar.sync %0, %1;" :: "r"(hid + 1), "r"(256) : "memory")

// ---- packed fp32x2 helpers (FFMA2 only reachable via PTX) ----
__device__ __forceinline__ void fma2(unsigned long long& d, unsigned long long a, unsigned long long b) {
    asm("fma.rn.f32x2 %0, %1, %2, %0;" : "+l"(d) : "l"(a), "l"(b));
}
__device__ __forceinline__ void add2(unsigned long long& d, unsigned long long a) {
    asm("add.rn.f32x2 %0, %0, %1;" : "+l"(d) : "l"(a));
}
__device__ __forceinline__ void upk2(unsigned long long v, float& a, float& b) {
    asm("mov.b64 {%0, %1}, %2;" : "=f"(a), "=f"(b) : "l"(v));
}

// ---------------- setup ----------------
__global__ void k_setup_a(const float* __restrict__ E0) {
    int tid = threadIdx.x;
    if (tid == 0) d_ctr = 0;
    if (tid < LL) {
        int best = 0; float bv = E0[tid * HN];
        for (int h = 1; h < HN; h++) {
            float v = E0[tid * HN + h];
            if (v > bv) { bv = v; best = h; }
        }
        d_bucket[tid] = best;
    }
    if (tid < NV) { d_deg[tid] = 0; d_fill[tid] = 0; }
}

__global__ void k_setup_b(const float* __restrict__ x, const int* __restrict__ ei) {
    int e = blockIdx.x * blockDim.x + threadIdx.x;
    if (e < NV) {
        int best = 0; float bv = x[e * LL];
        for (int l = 1; l < LL; l++) {
            float v = x[e * LL + l];
            if (v > bv) { bv = v; best = l; }
        }
        d_nb[e] = d_bucket[best];
    }
    if (e < E2) {
        int d = ei[e ^ EE];              // dst of directed edge e (sym trick)
        atomicAdd(&d_deg[d], 1);
    }
}

__global__ void k_scan() {
    __shared__ int s[NV];
    int tid = threadIdx.x;
    s[tid] = d_deg[tid];
    __syncthreads();
    for (int o = 1; o < NV; o <<= 1) {
        int v = (tid >= o) ? s[tid - o] : 0;
        __syncthreads();
        s[tid] += v;
        __syncthreads();
    }
    d_off[tid + 1] = s[tid];
    if (tid == 0) d_off[0] = 0;
}

__global__ void k_fill(const int* __restrict__ ei) {
    int e = blockIdx.x * blockDim.x + threadIdx.x;
    if (e < E2) {
        int s = ei[e];
        int d = ei[e ^ EE];
        int p = atomicAdd(&d_fill[d], 1);
        d_adj[d_off[d] + p] = s;
    }
}

// ---------------- 2-hop reach masks ----------------
__global__ void k_reach(const int* __restrict__ ei) {
    int r = blockIdx.x;
    int tid = threadIdx.x;
    __shared__ unsigned cur[16], nxt[16];
    if (tid < 16) cur[tid] = (tid == (r >> 5)) ? (1u << (r & 31)) : 0u;
    __syncthreads();
    for (int hop = 0; hop < 2; hop++) {
        if (tid < 16) nxt[tid] = cur[tid];
        __syncthreads();
        for (int e = tid; e < E2; e += blockDim.x) {
            int s = ei[e];
            if ((cur[s >> 5] >> (s & 31)) & 1u) {
                int d = ei[e ^ EE];
                atomicOr(&nxt[d >> 5], 1u << (d & 31));
            }
        }
        __syncthreads();
        if (tid < 16) cur[tid] = nxt[tid];
        __syncthreads();
    }
    if (tid < 16) d_mask[r * 16 + tid] = cur[tid];
}

// ---------------- helpers ----------------
__device__ __forceinline__ float4 warp_softmax4(float x0, float x1, float x2, float x3) {
    // softmax over 128 values (4 per lane, h = 4*lane + j), logits = (x - max)*10 (tau = 0.1)
    float m = fmaxf(fmaxf(x0, x1), fmaxf(x2, x3));
#pragma unroll
    for (int o = 16; o; o >>= 1) m = fmaxf(m, __shfl_xor_sync(0xffffffffu, m, o));
    float e0 = __expf((x0 - m) * 10.f);
    float e1 = __expf((x1 - m) * 10.f);
    float e2 = __expf((x2 - m) * 10.f);
    float e3 = __expf((x3 - m) * 10.f);
    float s = e0 + e1 + e2 + e3;
#pragma unroll
    for (int o = 16; o; o >>= 1) s += __shfl_xor_sync(0xffffffffu, s, o);
    float inv = 1.f / s;
    return make_float4(e0 * inv, e1 * inv, e2 * inv, e3 * inv);
}

// duplicated writeback: dst = row base + 8*lane
__device__ __forceinline__ void store_dup(float* dst, float4 c) {
    *(float4*)(dst)     = make_float4(c.x, c.x, c.y, c.y);
    *(float4*)(dst + 4) = make_float4(c.z, c.z, c.w, c.w);
}

// ---------------- ego WL features (the hot kernel) ----------------
// PERSISTENT: 148 blocks; R1/R2 staged once per block in 131KB dynamic smem.
// Each 256-thread half independently grabs roots from d_ctr (dynamic balance).
// Inner z-GEMM: fma.rn.f32x2 with zero packing MOVs (ulonglong2 loads + duplicated C/U).
__global__ void __launch_bounds__(512) k_ego(const float* __restrict__ R) {
    extern __shared__ __align__(16) float Rs[];          // [2*HN*HN]
    __shared__ unsigned msk[2][16];
    __shared__ unsigned short act[2][NV];
    __shared__ int woff[2][17];
    __shared__ float facc[2][4 * HN];
    __shared__ int nb_s[NV];
    __shared__ int cur_r[2];

    int tid = threadIdx.x;
    int hid = tid >> 8;           // which half (independent worker)
    int ltid = tid & 255;
    int lane = tid & 31, w8 = ltid >> 5;

    // cooperative: stage R into smem, cache node buckets (once per block)
    {
        const float4* R4 = (const float4*)R;
        float4* Rs4 = (float4*)Rs;
        for (int j = tid; j < 2 * HN * HN / 4; j += 512) Rs4[j] = R4[j];
        for (int j = tid; j < NV; j += 512) nb_s[j] = d_nb[j];
    }
    __syncthreads();

    while (true) {
        if (ltid == 0) cur_r[hid] = atomicAdd(&d_ctr, 1);
        HBAR();
        int r = cur_r[hid];
        if (r >= NV) break;       // uniform within the half

        if (ltid < 16) msk[hid][ltid] = d_mask[r * 16 + ltid];
        for (int j = ltid; j < 4 * HN; j += 256) facc[hid][j] = 0.f;
        HBAR();

        if (ltid == 0) {
            int s = 0;
            for (int k = 0; k < 16; k++) { woff[hid][k] = s; s += __popc(msk[hid][k]); }
            woff[hid][16] = s;
        }
        HBAR();
        if (ltid < 16) {
            unsigned m = msk[hid][ltid];
            int p = woff[hid][ltid];
            while (m) { int b = __ffs(m) - 1; m &= m - 1; act[hid][p++] = (unsigned short)(ltid * 32 + b); }
        }
        HBAR();
        int n_act = woff[hid][16];

        float* Cb = d_C + (size_t)r * NV * CH;
        float* Ub = d_U + (size_t)r * NV * CH;

        // feats[0] = masked bucket histogram
        for (int a = ltid; a < n_act; a += 256) atomicAdd(&facc[hid][nb_s[act[hid][a]]], 1.f);

        // ---- iteration 1: sparse (c0 is one-hot): z = R1[nb_i] + sum_nbr R2[nb_s] ----
        {
            float4 wacc = make_float4(0.f, 0.f, 0.f, 0.f);
            for (int a = w8; a < n_act; a += 8) {
                int i = act[hid][a];
                ulonglong2 z0 = *(const ulonglong2*)(Rs + nb_s[i] * HN + lane * 4);
                unsigned long long za = z0.x, zb = z0.y;
                int e0 = d_off[i], e1 = d_off[i + 1];
                for (int e = e0; e < e1; e++) {
                    int s = d_adj[e];
                    if ((msk[hid][s >> 5] >> (s & 31)) & 1u) {
                        ulonglong2 rr = *(const ulonglong2*)(Rs + (HN + nb_s[s]) * HN + lane * 4);
                        add2(za, rr.x);
                        add2(zb, rr.y);
                    }
                }
                float zx, zy, zz, zw;
                upk2(za, zx, zy); upk2(zb, zz, zw);
                float4 c = warp_softmax4(zx, zy, zz, zw);
                store_dup(Cb + (size_t)i * CH + 8 * lane, c);
                wacc.x += c.x; wacc.y += c.y; wacc.z += c.z; wacc.w += c.w;
            }
            atomicAdd(&facc[hid][HN + lane * 4 + 0], wacc.x);
            atomicAdd(&facc[hid][HN + lane * 4 + 1], wacc.y);
            atomicAdd(&facc[hid][HN + lane * 4 + 2], wacc.z);
            atomicAdd(&facc[hid][HN + lane * 4 + 3], wacc.w);
        }
        HBAR();

        // ---- iterations 2,3: dense z = c@R1 + u@R2 ----
        for (int t = 2; t <= 3; t++) {
            // pass A: neighbor sums u (duplicated layout in, duplicated out; packed adds)
            for (int a = w8; a < n_act; a += 8) {
                int i = act[hid][a];
                unsigned long long u0 = 0ull, u1 = 0ull, u2 = 0ull, u3 = 0ull;
                int e0 = d_off[i], e1 = d_off[i + 1];
                for (int e = e0; e < e1; e++) {
                    int s = d_adj[e];
                    if ((msk[hid][s >> 5] >> (s & 31)) & 1u) {
                        const float* src = Cb + (size_t)s * CH + 8 * lane;
                        ulonglong2 ca = *(const ulonglong2*)(src);
                        ulonglong2 cb = *(const ulonglong2*)(src + 4);
                        add2(u0, ca.x); add2(u1, ca.y);
                        add2(u2, cb.x); add2(u3, cb.y);
                    }
                }
                float* dst = Ub + (size_t)i * CH + 8 * lane;
                *(ulonglong2*)(dst)     = make_ulonglong2(u0, u1);
                *(ulonglong2*)(dst + 4) = make_ulonglong2(u2, u3);
            }
            HBAR();
            // pass B: z GEMM + softmax, 4 nodes per warp, k-blocked by 4, zero-MOV FFMA2 inner loop
            float4 wacc = make_float4(0.f, 0.f, 0.f, 0.f);
            for (int base = w8 * 4; base < n_act; base += 32) {
                int nv = n_act - base; if (nv > 4) nv = 4;
                const float* Cr[4];
                const float* Ur[4];
#pragma unroll
                for (int n = 0; n < 4; n++) {
                    int a = base + (n < nv ? n : 0);
                    int i = act[hid][a];
                    Cr[n] = Cb + (size_t)i * CH;
                    Ur[n] = Ub + (size_t)i * CH;
                }
                unsigned long long za[4], zb[4];
#pragma unroll
                for (int n = 0; n < 4; n++) { za[n] = 0ull; zb[n] = 0ull; }
                for (int k = 0; k < HN; k += 4) {
                    unsigned long long cp[4][4], up[4][4];
#pragma unroll
                    for (int n = 0; n < 4; n++) {
                        ulonglong2 cA = *(const ulonglong2*)(Cr[n] + 2 * k);
                        ulonglong2 cB = *(const ulonglong2*)(Cr[n] + 2 * k + 4);
                        ulonglong2 uA = *(const ulonglong2*)(Ur[n] + 2 * k);
                        ulonglong2 uB = *(const ulonglong2*)(Ur[n] + 2 * k + 4);
                        cp[n][0] = cA.x; cp[n][1] = cA.y; cp[n][2] = cB.x; cp[n][3] = cB.y;
                        up[n][0] = uA.x; up[n][1] = uA.y; up[n][2] = uB.x; up[n][3] = uB.y;
                    }
#pragma unroll
                    for (int kk = 0; kk < 4; kk++) {
                        ulonglong2 r1p = *(const ulonglong2*)(Rs + (k + kk) * HN + lane * 4);
                        ulonglong2 r2p = *(const ulonglong2*)(Rs + (HN + k + kk) * HN + lane * 4);
#pragma unroll
                        for (int n = 0; n < 4; n++) {
                            fma2(za[n], cp[n][kk], r1p.x);
                            fma2(za[n], up[n][kk], r2p.x);
                            fma2(zb[n], cp[n][kk], r1p.y);
                            fma2(zb[n], up[n][kk], r2p.y);
                        }
                    }
                }
                for (int n = 0; n < nv; n++) {
                    float zx, zy, zz, zw;
                    upk2(za[n], zx, zy); upk2(zb[n], zz, zw);
                    float4 c = warp_softmax4(zx, zy, zz, zw);
                    int i = act[hid][base + n];
                    store_dup(Cb + (size_t)i * CH + 8 * lane, c);
                    wacc.x += c.x; wacc.y += c.y; wacc.z += c.z; wacc.w += c.w;
                }
            }
            atomicAdd(&facc[hid][t * HN + lane * 4 + 0], wacc.x);
            atomicAdd(&facc[hid][t * HN + lane * 4 + 1], wacc.y);
            atomicAdd(&facc[hid][t * HN + lane * 4 + 2], wacc.z);
            atomicAdd(&facc[hid][t * HN + lane * 4 + 3], wacc.w);
            HBAR();
        }

        for (int j = ltid; j < 4 * HN; j += 256) d_ego[r * 4 * HN + j] = facc[hid][j];
        // loop-top HBAR orders these reads of facc before next root's zeroing
    }
}

// ---------------- filter-graph WL features ----------------
__global__ void __launch_bounds__(128) k_filt(const float* __restrict__ P,
                                              const float* __restrict__ X,
                                              const float* __restrict__ R) {
    int f = blockIdx.x;
    int tid = threadIdx.x, lane = tid & 31, w = tid >> 5;
    __shared__ float A[MM][MM];
    __shared__ int fb[MM];
    __shared__ float nmask[MM];
    __shared__ __align__(16) float c[MM][HN];
    __shared__ __align__(16) float u[MM][HN];
    __shared__ __align__(16) float zsh[MM][HN];
    __shared__ float feats[4][HN];
    __shared__ float red[4];

    if (tid < MM * MM) A[tid / MM][tid % MM] = P[f * MM * MM + tid];
    if (tid < MM) {
        int m = tid, best = 0;
        float bv = X[(f * MM + m) * LL];
        for (int l = 1; l < LL; l++) {
            float v = X[(f * MM + m) * LL + l];
            if (v > bv) { bv = v; best = l; }
        }
        fb[m] = d_bucket[best];
    }
    __syncthreads();
    if (tid == 0) {
        // largest connected component via synchronous min-label propagation
        float comp[MM], cn[MM];
        for (int m = 0; m < MM; m++) comp[m] = (float)m;
        for (int it = 0; it < MM; it++) {
            for (int m = 0; m < MM; m++) {
                float nm = 1e9f;
                for (int n = 0; n < MM; n++) if (A[m][n] > 0.f) nm = fminf(nm, comp[n]);
                cn[m] = fminf(comp[m], nm);
            }
            for (int m = 0; m < MM; m++) comp[m] = cn[m];
        }
        int counts[MM], ci[MM];
        for (int m = 0; m < MM; m++) counts[m] = 0;
        for (int m = 0; m < MM; m++) { ci[m] = (int)comp[m]; counts[ci[m]]++; }
        int best = 0;
        for (int m = 1; m < MM; m++) if (counts[m] > counts[best]) best = m;
        for (int m = 0; m < MM; m++) nmask[m] = (ci[m] == best) ? 1.f : 0.f;
    }
    __syncthreads();
    if (tid < MM * MM) A[tid / MM][tid % MM] *= nmask[tid / MM] * nmask[tid % MM];
    __syncthreads();

    int h = tid;
    float f0 = 0.f;
    for (int m = 0; m < MM; m++) {
        float v = (nmask[m] > 0.f && fb[m] == h) ? 1.f : 0.f;
        c[m][h] = v; f0 += v;
    }
    feats[0][h] = f0;
    __syncthreads();

    for (int t = 1; t <= 3; t++) {
        for (int m = 0; m < MM; m++) {
            float s = 0.f;
            for (int n = 0; n < MM; n++) s += A[m][n] * c[n][h];
            u[m][h] = s;
        }
        __syncthreads();
        float zr[MM];
#pragma unroll
        for (int m = 0; m < MM; m++) zr[m] = 0.f;
        for (int k = 0; k < HN; k++) {
            float r1 = R[k * HN + h], r2 = R[(HN + k) * HN + h];
#pragma unroll
            for (int m = 0; m < MM; m++) zr[m] += c[m][k] * r1 + u[m][k] * r2;
        }
#pragma unroll
        for (int m = 0; m < MM; m++) zsh[m][h] = zr[m];
        __syncthreads();
        for (int m = w; m < MM; m += 4) {
            float4 zv = *(const float4*)&zsh[m][lane * 4];
            float4 cc = warp_softmax4(zv.x, zv.y, zv.z, zv.w);
            float mk = nmask[m];
            c[m][lane * 4 + 0] = cc.x * mk;
            c[m][lane * 4 + 1] = cc.y * mk;
            c[m][lane * 4 + 2] = cc.z * mk;
            c[m][lane * 4 + 3] = cc.w * mk;
        }
        __syncthreads();
        float ft = 0.f;
        for (int m = 0; m < MM; m++) ft += c[m][h];
        feats[t][h] = ft;
        __syncthreads();
    }

    for (int t = 0; t < 4; t++) d_filt[f * 4 * HN + t * HN + h] = feats[t][h];
    float sq = 0.f;
    for (int t = 0; t < 4; t++) { float v = feats[t][h]; sq += v * v; }
#pragma unroll
    for (int o = 16; o; o >>= 1) sq += __shfl_xor_sync(0xffffffffu, sq, o);
    if (lane == 0) red[w] = sq;
    __syncthreads();
    if (tid == 0) d_nf[f] = sqrtf(red[0] + red[1] + red[2] + red[3]);
}

// ---------------- normalized similarity ----------------
__global__ void __launch_bounds__(128) k_sim(float* __restrict__ out) {
    int i = blockIdx.x;
    int tid = threadIdx.x, lane = tid & 31, w = tid >> 5;
    float acc[FF + 1];
#pragma unroll
    for (int f = 0; f <= FF; f++) acc[f] = 0.f;
    for (int j = tid; j < 4 * HN; j += 128) {
        float g = d_ego[i * 4 * HN + j];
        acc[FF] += g * g;
#pragma unroll
        for (int f = 0; f < FF; f++) acc[f] += g * d_filt[f * 4 * HN + j];
    }
#pragma unroll
    for (int f = 0; f <= FF; f++) {
#pragma unroll
        for (int o = 16; o; o >>= 1) acc[f] += __shfl_xor_sync(0xffffffffu, acc[f], o);
    }
    __shared__ float sred[4][FF + 1];
    if (lane == 0) {
        for (int f = 0; f <= FF; f++) sred[w][f] = acc[f];
    }
    __syncthreads();
    if (tid < FF + 1) {
        float v = sred[0][tid] + sred[1][tid] + sred[2][tid] + sred[3][tid];
        sred[0][tid] = v;
    }
    __syncthreads();
    if (tid < FF) {
        float ng = sqrtf(sred[0][FF]);
        out[i * FF + tid] = sred[0][tid] / (d_nf[tid] * ng + 1e-12f);
    }
}

// ---------------- launch ----------------
extern "C" void kernel_launch(void* const* d_in, const int* in_sizes, int n_in,
                              void* d_out, int out_size) {
    const float* x  = (const float*)d_in[0];   // [512,16]
    const int*   ei = (const int*)d_in[1];     // [2,2048]
    const float* P  = (const float*)d_in[2];   // [16,8,8]
    const float* X  = (const float*)d_in[3];   // [16,8,16]
    const float* E0 = (const float*)d_in[4];   // [16,128]
    const float* R  = (const float*)d_in[5];   // [256,128]
    float* out = (float*)d_out;                // [512,16]

    const int smem_r = 2 * HN * HN * (int)sizeof(float);   // 131072 B
    cudaFuncSetAttribute(k_ego, cudaFuncAttributeMaxDynamicSharedMemorySize, smem_r);

    k_setup_a<<<1, 512>>>(E0);
    k_setup_b<<<16, 256>>>(x, ei);
    k_scan<<<1, 512>>>();
    k_fill<<<16, 256>>>(ei);
    k_reach<<<512, 128>>>(ei);
    k_ego<<<NBLK, 512, smem_r>>>(R);
    k_filt<<<16, 128>>>(P, X, R);
    k_sim<<<512, 128>>>(out);
}

// round 11
// speedup vs baseline: 1.3659x; 1.3659x over previous
#include <cuda_runtime.h>

#define NV 512      // nodes
#define HN 128      // WL hash buckets
#define EE 2048     // original edges
#define E2 4096     // symmetrized directed edges
#define FF 16       // filter graphs
#define MM 8        // filter graph nodes
#define LL 16       // labels
#define NBLK 128    // k_ego grid: 128 blocks x 4 workers = 512 roots exactly

// ---- static device scratch (no allocation allowed) ----
// C/U non-duplicated: live footprint ~36MB (L2-resident; the duplicated layout
// measured 526us total).
__device__ __align__(16) float d_C[(size_t)NV * NV * HN];   // per-root WL labels (dense by node id)
__device__ __align__(16) float d_U[(size_t)NV * NV * HN];   // per-root neighbor sums
__device__ __align__(16) float d_ego[NV * 4 * HN];
__device__ __align__(16) float d_filt[FF * 4 * HN];
__device__ float d_nf[FF];
__device__ int d_deg[NV], d_off[NV + 1], d_fill[NV];
__device__ int d_adj[E2];
__device__ int d_nb[NV];        // node bucket index
__device__ int d_bucket[LL];    // label -> bucket
__device__ unsigned d_mask[NV * 16];   // per-root 512-bit reach mask

#define HBAR() asm volatile("bar.sync %0, %1;" :: "r"(hid + 1), "r"(128) : "memory")

// ---- packed fp32x2 helpers (FFMA2 only reachable via PTX) ----
__device__ __forceinline__ unsigned long long pk2(float a, float b) {
    unsigned long long r;
    asm("mov.b64 %0, {%1, %2};" : "=l"(r) : "f"(a), "f"(b));
    return r;
}
__device__ __forceinline__ void fma2(unsigned long long& d, unsigned long long a, unsigned long long b) {
    asm("fma.rn.f32x2 %0, %1, %2, %0;" : "+l"(d) : "l"(a), "l"(b));
}
__device__ __forceinline__ void add2(unsigned long long& d, unsigned long long a) {
    asm("add.rn.f32x2 %0, %0, %1;" : "+l"(d) : "l"(a));
}
__device__ __forceinline__ void upk2(unsigned long long v, float& a, float& b) {
    asm("mov.b64 {%0, %1}, %2;" : "=f"(a), "=f"(b) : "l"(v));
}

// ---------------- setup ----------------
__global__ void k_setup_a(const float* __restrict__ E0) {
    int tid = threadIdx.x;
    if (tid < LL) {
        int best = 0; float bv = E0[tid * HN];
        for (int h = 1; h < HN; h++) {
            float v = E0[tid * HN + h];
            if (v > bv) { bv = v; best = h; }
        }
        d_bucket[tid] = best;
    }
    if (tid < NV) { d_deg[tid] = 0; d_fill[tid] = 0; }
}

__global__ void k_setup_b(const float* __restrict__ x, const int* __restrict__ ei) {
    int e = blockIdx.x * blockDim.x + threadIdx.x;
    if (e < NV) {
        int best = 0; float bv = x[e * LL];
        for (int l = 1; l < LL; l++) {
            float v = x[e * LL + l];
            if (v > bv) { bv = v; best = l; }
        }
        d_nb[e] = d_bucket[best];
    }
    if (e < E2) {
        int d = ei[e ^ EE];              // dst of directed edge e (sym trick)
        atomicAdd(&d_deg[d], 1);
    }
}

__global__ void k_scan() {
    __shared__ int s[NV];
    int tid = threadIdx.x;
    s[tid] = d_deg[tid];
    __syncthreads();
    for (int o = 1; o < NV; o <<= 1) {
        int v = (tid >= o) ? s[tid - o] : 0;
        __syncthreads();
        s[tid] += v;
        __syncthreads();
    }
    d_off[tid + 1] = s[tid];
    if (tid == 0) d_off[0] = 0;
}

__global__ void k_fill(const int* __restrict__ ei) {
    int e = blockIdx.x * blockDim.x + threadIdx.x;
    if (e < E2) {
        int s = ei[e];
        int d = ei[e ^ EE];
        int p = atomicAdd(&d_fill[d], 1);
        d_adj[d_off[d] + p] = s;
    }
}

// ---------------- 2-hop reach masks ----------------
__global__ void k_reach(const int* __restrict__ ei) {
    int r = blockIdx.x;
    int tid = threadIdx.x;
    __shared__ unsigned cur[16], nxt[16];
    if (tid < 16) cur[tid] = (tid == (r >> 5)) ? (1u << (r & 31)) : 0u;
    __syncthreads();
    for (int hop = 0; hop < 2; hop++) {
        if (tid < 16) nxt[tid] = cur[tid];
        __syncthreads();
        for (int e = tid; e < E2; e += blockDim.x) {
            int s = ei[e];
            if ((cur[s >> 5] >> (s & 31)) & 1u) {
                int d = ei[e ^ EE];
                atomicOr(&nxt[d >> 5], 1u << (d & 31));
            }
        }
        __syncthreads();
        if (tid < 16) cur[tid] = nxt[tid];
        __syncthreads();
    }
    if (tid < 16) d_mask[r * 16 + tid] = cur[tid];
}

// ---------------- helpers ----------------
__device__ __forceinline__ float4 warp_softmax4(float x0, float x1, float x2, float x3) {
    // softmax over 128 values (4 per lane, h = 4*lane + j), logits = (x - max)*10 (tau = 0.1)
    float m = fmaxf(fmaxf(x0, x1), fmaxf(x2, x3));
#pragma unroll
    for (int o = 16; o; o >>= 1) m = fmaxf(m, __shfl_xor_sync(0xffffffffu, m, o));
    float e0 = __expf((x0 - m) * 10.f);
    float e1 = __expf((x1 - m) * 10.f);
    float e2 = __expf((x2 - m) * 10.f);
    float e3 = __expf((x3 - m) * 10.f);
    float s = e0 + e1 + e2 + e3;
#pragma unroll
    for (int o = 16; o; o >>= 1) s += __shfl_xor_sync(0xffffffffu, s, o);
    float inv = 1.f / s;
    return make_float4(e0 * inv, e1 * inv, e2 * inv, e3 * inv);
}

// ---------------- ego WL features (the hot kernel) ----------------
// 128 blocks x 4 independent 128-thread workers = 512 workers; worker w handles root w.
// R1/R2 staged once per block in 131KB dynamic smem. C/U non-duplicated (L2-resident footprint).
__global__ void __launch_bounds__(512) k_ego(const float* __restrict__ R) {
    extern __shared__ __align__(16) float Rs[];          // [2*HN*HN]
    __shared__ unsigned msk[4][16];
    __shared__ unsigned short act[4][NV];
    __shared__ int woff[4][17];
    __shared__ float facc[4][4 * HN];
    __shared__ int nb_s[NV];

    int tid = threadIdx.x;
    int hid = tid >> 7;           // worker id within block (0..3)
    int ltid = tid & 127;
    int lane = tid & 31, w4 = ltid >> 5;   // 4 warps per worker

    // cooperative: stage R into smem, cache node buckets (once per block)
    {
        const float4* R4 = (const float4*)R;
        float4* Rs4 = (float4*)Rs;
        for (int j = tid; j < 2 * HN * HN / 4; j += 512) Rs4[j] = R4[j];
        for (int j = tid; j < NV; j += 512) nb_s[j] = d_nb[j];
    }
    __syncthreads();

    int r = blockIdx.x * 4 + hid;          // static 1 root per worker

    if (ltid < 16) msk[hid][ltid] = d_mask[r * 16 + ltid];
    for (int j = ltid; j < 4 * HN; j += 128) facc[hid][j] = 0.f;
    HBAR();

    if (ltid == 0) {
        int s = 0;
        for (int k = 0; k < 16; k++) { woff[hid][k] = s; s += __popc(msk[hid][k]); }
        woff[hid][16] = s;
    }
    HBAR();
    if (ltid < 16) {
        unsigned m = msk[hid][ltid];
        int p = woff[hid][ltid];
        while (m) { int b = __ffs(m) - 1; m &= m - 1; act[hid][p++] = (unsigned short)(ltid * 32 + b); }
    }
    HBAR();
    int n_act = woff[hid][16];

    float* Cb = d_C + (size_t)r * NV * HN;
    float* Ub = d_U + (size_t)r * NV * HN;

    // feats[0] = masked bucket histogram
    for (int a = ltid; a < n_act; a += 128) atomicAdd(&facc[hid][nb_s[act[hid][a]]], 1.f);

    // ---- iteration 1: sparse (c0 is one-hot): z = R1[nb_i] + sum_nbr R2[nb_s] ----
    {
        float4 wacc = make_float4(0.f, 0.f, 0.f, 0.f);
        for (int a = w4; a < n_act; a += 4) {
            int i = act[hid][a];
            ulonglong2 z0 = *(const ulonglong2*)(Rs + nb_s[i] * HN + lane * 4);
            unsigned long long za = z0.x, zb = z0.y;
            int e0 = d_off[i], e1 = d_off[i + 1];
            for (int e = e0; e < e1; e++) {
                int s = d_adj[e];
                if ((msk[hid][s >> 5] >> (s & 31)) & 1u) {
                    ulonglong2 rr = *(const ulonglong2*)(Rs + (HN + nb_s[s]) * HN + lane * 4);
                    add2(za, rr.x);
                    add2(zb, rr.y);
                }
            }
            float zx, zy, zz, zw;
            upk2(za, zx, zy); upk2(zb, zz, zw);
            float4 c = warp_softmax4(zx, zy, zz, zw);
            *(float4*)(Cb + (size_t)i * HN + lane * 4) = c;
            wacc.x += c.x; wacc.y += c.y; wacc.z += c.z; wacc.w += c.w;
        }
        atomicAdd(&facc[hid][HN + lane * 4 + 0], wacc.x);
        atomicAdd(&facc[hid][HN + lane * 4 + 1], wacc.y);
        atomicAdd(&facc[hid][HN + lane * 4 + 2], wacc.z);
        atomicAdd(&facc[hid][HN + lane * 4 + 3], wacc.w);
    }
    HBAR();

    // ---- iterations 2,3: dense z = c@R1 + u@R2 ----
    for (int t = 2; t <= 3; t++) {
        // pass A: neighbor sums u (2-way edge unroll for MLP)
        for (int a = w4; a < n_act; a += 4) {
            int i = act[hid][a];
            float4 uA = make_float4(0.f, 0.f, 0.f, 0.f);
            float4 uB = make_float4(0.f, 0.f, 0.f, 0.f);
            int e0 = d_off[i], e1 = d_off[i + 1];
            int e = e0;
            for (; e + 1 < e1; e += 2) {
                int s0 = d_adj[e], s1 = d_adj[e + 1];
                bool m0 = (msk[hid][s0 >> 5] >> (s0 & 31)) & 1u;
                bool m1 = (msk[hid][s1 >> 5] >> (s1 & 31)) & 1u;
                if (m0) {
                    float4 cc = *(const float4*)(Cb + (size_t)s0 * HN + lane * 4);
                    uA.x += cc.x; uA.y += cc.y; uA.z += cc.z; uA.w += cc.w;
                }
                if (m1) {
                    float4 cc = *(const float4*)(Cb + (size_t)s1 * HN + lane * 4);
                    uB.x += cc.x; uB.y += cc.y; uB.z += cc.z; uB.w += cc.w;
                }
            }
            if (e < e1) {
                int s0 = d_adj[e];
                if ((msk[hid][s0 >> 5] >> (s0 & 31)) & 1u) {
                    float4 cc = *(const float4*)(Cb + (size_t)s0 * HN + lane * 4);
                    uA.x += cc.x; uA.y += cc.y; uA.z += cc.z; uA.w += cc.w;
                }
            }
            uA.x += uB.x; uA.y += uB.y; uA.z += uB.z; uA.w += uB.w;
            *(float4*)(Ub + (size_t)i * HN + lane * 4) = uA;
        }
        HBAR();
        // pass B: z GEMM + softmax, 4 nodes per warp, k-blocked by 4, FFMA2 inner loop
        float4 wacc = make_float4(0.f, 0.f, 0.f, 0.f);
        for (int base = w4 * 4; base < n_act; base += 16) {
            int nv = n_act - base; if (nv > 4) nv = 4;
            const float* Cr[4];
            const float* Ur[4];
#pragma unroll
            for (int n = 0; n < 4; n++) {
                int a = base + (n < nv ? n : 0);
                int i = act[hid][a];
                Cr[n] = Cb + (size_t)i * HN;
                Ur[n] = Ub + (size_t)i * HN;
            }
            unsigned long long za[4], zb[4];
#pragma unroll
            for (int n = 0; n < 4; n++) { za[n] = 0ull; zb[n] = 0ull; }
            for (int k = 0; k < HN; k += 4) {
                float4 c4[4], u4[4];
#pragma unroll
                for (int n = 0; n < 4; n++) {
                    c4[n] = *(const float4*)(Cr[n] + k);
                    u4[n] = *(const float4*)(Ur[n] + k);
                }
#pragma unroll
                for (int kk = 0; kk < 4; kk++) {
                    ulonglong2 r1p = *(const ulonglong2*)(Rs + (k + kk) * HN + lane * 4);
                    ulonglong2 r2p = *(const ulonglong2*)(Rs + (HN + k + kk) * HN + lane * 4);
#pragma unroll
                    for (int n = 0; n < 4; n++) {
                        float ck = ((const float*)&c4[n])[kk];
                        float uk = ((const float*)&u4[n])[kk];
                        unsigned long long cp = pk2(ck, ck);
                        unsigned long long up = pk2(uk, uk);
                        fma2(za[n], cp, r1p.x);
                        fma2(za[n], up, r2p.x);
                        fma2(zb[n], cp, r1p.y);
                        fma2(zb[n], up, r2p.y);
                    }
                }
            }
            for (int n = 0; n < nv; n++) {
                float zx, zy, zz, zw;
                upk2(za[n], zx, zy); upk2(zb[n], zz, zw);
                float4 c = warp_softmax4(zx, zy, zz, zw);
                int i = act[hid][base + n];
                *(float4*)(Cb + (size_t)i * HN + lane * 4) = c;
                wacc.x += c.x; wacc.y += c.y; wacc.z += c.z; wacc.w += c.w;
            }
        }
        atomicAdd(&facc[hid][t * HN + lane * 4 + 0], wacc.x);
        atomicAdd(&facc[hid][t * HN + lane * 4 + 1], wacc.y);
        atomicAdd(&facc[hid][t * HN + lane * 4 + 2], wacc.z);
        atomicAdd(&facc[hid][t * HN + lane * 4 + 3], wacc.w);
        HBAR();
    }

    for (int j = ltid; j < 4 * HN; j += 128) d_ego[r * 4 * HN + j] = facc[hid][j];
}

// ---------------- filter-graph WL features ----------------
__global__ void __launch_bounds__(128) k_filt(const float* __restrict__ P,
                                              const float* __restrict__ X,
                                              const float* __restrict__ R) {
    int f = blockIdx.x;
    int tid = threadIdx.x, lane = tid & 31, w = tid >> 5;
    __shared__ float A[MM][MM];
    __shared__ int fb[MM];
    __shared__ float nmask[MM];
    __shared__ __align__(16) float c[MM][HN];
    __shared__ __align__(16) float u[MM][HN];
    __shared__ __align__(16) float zsh[MM][HN];
    __shared__ float feats[4][HN];
    __shared__ float red[4];

    if (tid < MM * MM) A[tid / MM][tid % MM] = P[f * MM * MM + tid];
    if (tid < MM) {
        int m = tid, best = 0;
        float bv = X[(f * MM + m) * LL];
        for (int l = 1; l < LL; l++) {
            float v = X[(f * MM + m) * LL + l];
            if (v > bv) { bv = v; best = l; }
        }
        fb[m] = d_bucket[best];
    }
    __syncthreads();
    if (tid == 0) {
        // largest connected component via synchronous min-label propagation
        float comp[MM], cn[MM];
        for (int m = 0; m < MM; m++) comp[m] = (float)m;
        for (int it = 0; it < MM; it++) {
            for (int m = 0; m < MM; m++) {
                float nm = 1e9f;
                for (int n = 0; n < MM; n++) if (A[m][n] > 0.f) nm = fminf(nm, comp[n]);
                cn[m] = fminf(comp[m], nm);
            }
            for (int m = 0; m < MM; m++) comp[m] = cn[m];
        }
        int counts[MM], ci[MM];
        for (int m = 0; m < MM; m++) counts[m] = 0;
        for (int m = 0; m < MM; m++) { ci[m] = (int)comp[m]; counts[ci[m]]++; }
        int best = 0;
        for (int m = 1; m < MM; m++) if (counts[m] > counts[best]) best = m;
        for (int m = 0; m < MM; m++) nmask[m] = (ci[m] == best) ? 1.f : 0.f;
    }
    __syncthreads();
    if (tid < MM * MM) A[tid / MM][tid % MM] *= nmask[tid / MM] * nmask[tid % MM];
    __syncthreads();

    int h = tid;
    float f0 = 0.f;
    for (int m = 0; m < MM; m++) {
        float v = (nmask[m] > 0.f && fb[m] == h) ? 1.f : 0.f;
        c[m][h] = v; f0 += v;
    }
    feats[0][h] = f0;
    __syncthreads();

    for (int t = 1; t <= 3; t++) {
        for (int m = 0; m < MM; m++) {
            float s = 0.f;
            for (int n = 0; n < MM; n++) s += A[m][n] * c[n][h];
            u[m][h] = s;
        }
        __syncthreads();
        float zr[MM];
#pragma unroll
        for (int m = 0; m < MM; m++) zr[m] = 0.f;
        for (int k = 0; k < HN; k++) {
            float r1 = R[k * HN + h], r2 = R[(HN + k) * HN + h];
#pragma unroll
            for (int m = 0; m < MM; m++) zr[m] += c[m][k] * r1 + u[m][k] * r2;
        }
#pragma unroll
        for (int m = 0; m < MM; m++) zsh[m][h] = zr[m];
        __syncthreads();
        for (int m = w; m < MM; m += 4) {
            float4 zv = *(const float4*)&zsh[m][lane * 4];
            float4 cc = warp_softmax4(zv.x, zv.y, zv.z, zv.w);
            float mk = nmask[m];
            c[m][lane * 4 + 0] = cc.x * mk;
            c[m][lane * 4 + 1] = cc.y * mk;
            c[m][lane * 4 + 2] = cc.z * mk;
            c[m][lane * 4 + 3] = cc.w * mk;
        }
        __syncthreads();
        float ft = 0.f;
        for (int m = 0; m < MM; m++) ft += c[m][h];
        feats[t][h] = ft;
        __syncthreads();
    }

    for (int t = 0; t < 4; t++) d_filt[f * 4 * HN + t * HN + h] = feats[t][h];
    float sq = 0.f;
    for (int t = 0; t < 4; t++) { float v = feats[t][h]; sq += v * v; }
#pragma unroll
    for (int o = 16; o; o >>= 1) sq += __shfl_xor_sync(0xffffffffu, sq, o);
    if (lane == 0) red[w] = sq;
    __syncthreads();
    if (tid == 0) d_nf[f] = sqrtf(red[0] + red[1] + red[2] + red[3]);
}

// ---------------- normalized similarity ----------------
__global__ void __launch_bounds__(128) k_sim(float* __restrict__ out) {
    int i = blockIdx.x;
    int tid = threadIdx.x, lane = tid & 31, w = tid >> 5;
    float acc[FF + 1];
#pragma unroll
    for (int f = 0; f <= FF; f++) acc[f] = 0.f;
    for (int j = tid; j < 4 * HN; j += 128) {
        float g = d_ego[i * 4 * HN + j];
        acc[FF] += g * g;
#pragma unroll
        for (int f = 0; f < FF; f++) acc[f] += g * d_filt[f * 4 * HN + j];
    }
#pragma unroll
    for (int f = 0; f <= FF; f++) {
#pragma unroll
        for (int o = 16; o; o >>= 1) acc[f] += __shfl_xor_sync(0xffffffffu, acc[f], o);
    }
    __shared__ float sred[4][FF + 1];
    if (lane == 0) {
        for (int f = 0; f <= FF; f++) sred[w][f] = acc[f];
    }
    __syncthreads();
    if (tid < FF + 1) {
        float v = sred[0][tid] + sred[1][tid] + sred[2][tid] + sred[3][tid];
        sred[0][tid] = v;
    }
    __syncthreads();
    if (tid < FF) {
        float ng = sqrtf(sred[0][FF]);
        out[i * FF + tid] = sred[0][tid] / (d_nf[tid] * ng + 1e-12f);
    }
}

// ---------------- launch ----------------
extern "C" void kernel_launch(void* const* d_in, const int* in_sizes, int n_in,
                              void* d_out, int out_size) {
    const float* x  = (const float*)d_in[0];   // [512,16]
    const int*   ei = (const int*)d_in[1];     // [2,2048]
    const float* P  = (const float*)d_in[2];   // [16,8,8]
    const float* X  = (const float*)d_in[3];   // [16,8,16]
    const float* E0 = (const float*)d_in[4];   // [16,128]
    const float* R  = (const float*)d_in[5];   // [256,128]
    float* out = (float*)d_out;                // [512,16]

    const int smem_r = 2 * HN * HN * (int)sizeof(float);   // 131072 B
    cudaFuncSetAttribute(k_ego, cudaFuncAttributeMaxDynamicSharedMemorySize, smem_r);

    k_setup_a<<<1, 512>>>(E0);
    k_setup_b<<<16, 256>>>(x, ei);
    k_scan<<<1, 512>>>();
    k_fill<<<16, 256>>>(ei);
    k_reach<<<512, 128>>>(ei);
    k_ego<<<NBLK, 512, smem_r>>>(R);
    k_filt<<<16, 128>>>(P, X, R);
    k_sim<<<512, 128>>>(out);
}